// round 16
// baseline (speedup 1.0000x reference)
#include <cuda_runtime.h>
#include <cuda_fp16.h>
#include <cstdint>

#define DZ 32
#define L2E 1.4426950408889634f

// ---------------------------------------------------------------------------
// Static device scratch (no runtime allocation allowed)
// g_mu_hi: per mu row n: 16 dwords (half2 k-pairs), position 4*(p&3)+(p>>2)
// holds k-pair p -> thread l4 reads pairs {l4,l4+4,l4+8,l4+12} as one
// contiguous 16-byte LDG.128. Values: w = mu_hat*kappa*log2e in fp16.
// (mu lo-residual dropped: cross term averages to ~1e-5 absolute on the
//  final mean -> far under tolerance; verified R15 rel_err 1.2e-6.)
// ---------------------------------------------------------------------------
__device__ uint32_t g_mu_hi[4096 * 16];
__device__ float g_partials[1024];
__device__ int   g_ticket;            // zero-init; reset by last block each run

static __device__ __forceinline__ float ex2f(float x) {
    float r; asm("ex2.approx.f32 %0, %1;" : "=f"(r) : "f"(x)); return r;
}
// m16n8k16 fp16 MMA, f32 accumulate
static __device__ __forceinline__ void mma16(float* d, const uint32_t* a,
                                             uint32_t b0, uint32_t b1) {
    asm volatile(
        "mma.sync.aligned.m16n8k16.row.col.f32.f16.f16.f32 "
        "{%0,%1,%2,%3},{%4,%5,%6,%7},{%8,%9},{%0,%1,%2,%3};"
        : "+f"(d[0]), "+f"(d[1]), "+f"(d[2]), "+f"(d[3])
        : "r"(a[0]), "r"(a[1]), "r"(a[2]), "r"(a[3]), "r"(b0), "r"(b1));
}
// m16n8k16 fp16 MMA, fp16 accumulate (prefilter)
static __device__ __forceinline__ void mma16h(uint32_t* d, const uint32_t* a,
                                              uint32_t b0, uint32_t b1) {
    asm volatile(
        "mma.sync.aligned.m16n8k16.row.col.f16.f16.f16.f16 "
        "{%0,%1},{%2,%3,%4,%5},{%6,%7},{%0,%1};"
        : "+r"(d[0]), "+r"(d[1])
        : "r"(a[0]), "r"(a[1]), "r"(a[2]), "r"(a[3]), "r"(b0), "r"(b1));
}

// ---------------------------------------------------------------------------
// Prep: normalize mu, scale by kappa*log2e, fp16, store hi plane with the
// k-pair interleave. One warp per row.
// ---------------------------------------------------------------------------
__global__ void vmf_prep_mu(const float* __restrict__ mu,
                            const float* __restrict__ kap_p, int B)
{
    const int n = (blockIdx.x * blockDim.x + threadIdx.x) >> 5;
    const int k = threadIdx.x & 31;
    if (n >= B) return;

    float v = __ldg(mu + (size_t)n * DZ + k);
    float ss = v * v;
    #pragma unroll
    for (int o = 16; o > 0; o >>= 1) ss += __shfl_xor_sync(0xFFFFFFFFu, ss, o);
    float r = rsqrtf(ss);
    r = r * fmaf(-0.5f * ss * r, r, 1.5f);           // Newton -> ~1e-7 rel
    float w = v * r * (__ldg(kap_p) * L2E);

    uint32_t hs = (uint32_t)__half_as_ushort(__float2half_rn(w));
    uint32_t h0 = __shfl_sync(0xFFFFFFFFu, hs, (k * 2) & 31);
    uint32_t h1 = __shfl_sync(0xFFFFFFFFu, hs, (k * 2 + 1) & 31);
    if (k < 16) {
        const int pos = 4 * (k & 3) + (k >> 2);      // k-pair interleave
        g_mu_hi[n * 16 + pos] = h0 | (h1 << 16);
    }
}

// ---------------------------------------------------------------------------
// Main: 128 z rows/CTA (8 warps x ONE m16 tile each), grid 512. Barrier-free
// mainloop streaming the mu hi-plane (128KB, L1-resident) via LDG.128.
// Each iteration covers 16 mu: 2 LDG.128 + 4 fp16-accum MMAs (2 independent
// chains) + merged max + ONE vote. Accepted (~11% of 16-blocks): 8 f32-accum
// MMAs + ex2-accumulate for both halves. Last block reduces partials -> out.
// ---------------------------------------------------------------------------
__global__ void __launch_bounds__(256, 4) vmf_main(
    const float* __restrict__ mu, const float* __restrict__ z,
    const float* __restrict__ kap_p,
    const float* __restrict__ lck_p, const float* __restrict__ lcz_p,
    float* __restrict__ out, int B, int NC, int ns)
{
    __shared__ float s_red[8];
    __shared__ int   s_last;

    const int tid  = threadIdx.x;
    const int wid  = tid >> 5;
    const int lane = tid & 31;
    const int g    = lane >> 2;
    const int l4   = lane & 3;

    if (tid == 0) s_last = 0;

    const float ke   = __ldg(kap_p) * L2E;
    const float bias = -ke;

    // ---- parent mu_hat for this warp's 16 z rows (all share one parent;
    //      zr mod 32 in {0,16} so the 16 rows never straddle a parent) ----
    const int zr = blockIdx.x * 128 + wid * 16;
    float mh = 0.f;
    const bool uniform_parent = (ns == 32);
    if (uniform_parent) {
        float m = __ldg(mu + (size_t)(zr >> 5) * DZ + lane);
        float ss = m * m;
        #pragma unroll
        for (int o = 16; o > 0; o >>= 1) ss += __shfl_xor_sync(0xFFFFFFFFu, ss, o);
        float r = rsqrtf(ss);
        r = r * fmaf(-0.5f * ss * r, r, 1.5f);
        mh = m * r;
    }

    // ---- A fragments (fp16 hi/lo split of z, one m16 tile) + parent dots ----
    uint32_t ahi[2][4], alo[2][4];
    float dq[2] = {0.f, 0.f};
    {
        const int r0 = zr + g;
        const int r1 = r0 + 8;
        #pragma unroll
        for (int e = 0; e < 4; e++) {
            const int c2 = l4 + 4 * e;
            float2 f0 = __ldg((const float2*)(z + (size_t)r0 * DZ) + c2);
            float2 f1 = __ldg((const float2*)(z + (size_t)r1 * DZ) + c2);
            float mv0 = __shfl_sync(0xFFFFFFFFu, mh, (2 * c2) & 31);
            float mv1 = __shfl_sync(0xFFFFFFFFu, mh, (2 * c2 + 1) & 31);
            dq[0] += mv0 * f0.x + mv1 * f0.y;
            dq[1] += mv0 * f1.x + mv1 * f1.y;
            __half2 h0 = __floats2half2_rn(f0.x, f0.y);
            __half2 h1 = __floats2half2_rn(f1.x, f1.y);
            __half2 e0 = __floats2half2_rn(f0.x - __half2float(__low2half(h0)),
                                           f0.y - __half2float(__high2half(h0)));
            __half2 e1 = __floats2half2_rn(f1.x - __half2float(__low2half(h1)),
                                           f1.y - __half2float(__high2half(h1)));
            const int kb = e >> 1, half = e & 1;
            ahi[kb][half * 2 + 0] = *(uint32_t*)&h0;
            ahi[kb][half * 2 + 1] = *(uint32_t*)&h1;
            alo[kb][half * 2 + 0] = *(uint32_t*)&e0;
            alo[kb][half * 2 + 1] = *(uint32_t*)&e1;
        }
    }
    // per-row thresholds (raw logit scale: ke*dot_parent - 41), as half
    __half thrh[2];
    #pragma unroll
    for (int q = 0; q < 2; q++) {
        float d = dq[q];
        d += __shfl_xor_sync(0xFFFFFFFFu, d, 1);
        d += __shfl_xor_sync(0xFFFFFFFFu, d, 2);
        thrh[q] = __float2half(uniform_parent ? (ke * d - 41.0f) : -1e30f);
    }

    // ---- barrier-free mainloop: 16 mu per iteration, one vote each ----
    const uint4* __restrict__ mu_base =
        (const uint4*)(g_mu_hi + (size_t)g * 16 + (size_t)l4 * 4);
    // row n -> uint4 index n*4 (row stride 16 dwords = 4 uint4)

    float acc[2] = {0.f, 0.f};

    #pragma unroll 8
    for (int n = 0; n < B; n += 16) {
        const uint4 b0 = __ldg(mu_base + (size_t)n * 4);        // mu n..n+7
        const uint4 b1 = __ldg(mu_base + (size_t)n * 4 + 32);   // mu n+8..n+15

        // fp16-accum prefilter: two independent 2-chains
        uint32_t D0[2] = {0u, 0u}, D1[2] = {0u, 0u};
        mma16h(D0, ahi[0], b0.x, b0.y);
        mma16h(D0, ahi[1], b0.z, b0.w);
        mma16h(D1, ahi[0], b1.x, b1.y);
        mma16h(D1, ahi[1], b1.z, b1.w);

        __half2 m2 = __hmax2(__hmax2(*(__half2*)&D0[0], *(__half2*)&D0[1]),
                             __hmax2(*(__half2*)&D1[0], *(__half2*)&D1[1]));
        bool p = __hgt(__low2half(m2),  thrh[0]) |
                 __hgt(__high2half(m2), thrh[1]);

        if (__any_sync(0xFFFFFFFFu, p)) {
            float c0[4] = {bias, bias, bias, bias};
            float c1[4] = {bias, bias, bias, bias};
            mma16(c0, ahi[0], b0.x, b0.y);
            mma16(c0, ahi[1], b0.z, b0.w);
            mma16(c0, alo[0], b0.x, b0.y);
            mma16(c0, alo[1], b0.z, b0.w);
            mma16(c1, ahi[0], b1.x, b1.y);
            mma16(c1, ahi[1], b1.z, b1.w);
            mma16(c1, alo[0], b1.x, b1.y);
            mma16(c1, alo[1], b1.z, b1.w);
            acc[0] += (ex2f(c0[0]) + ex2f(c0[1])) + (ex2f(c1[0]) + ex2f(c1[1]));
            acc[1] += (ex2f(c0[2]) + ex2f(c0[3])) + (ex2f(c1[2]) + ex2f(c1[3]));
        }
    }

    // ---- quad reduce (mu cols), ln, butterfly over the 8 g-groups ----
    #pragma unroll
    for (int q = 0; q < 2; q++) {
        acc[q] += __shfl_xor_sync(0xFFFFFFFFu, acc[q], 1);
        acc[q] += __shfl_xor_sync(0xFFFFFFFFu, acc[q], 2);
    }
    float lv = logf(fmaxf(acc[0], 1e-38f)) + logf(fmaxf(acc[1], 1e-38f));
    #pragma unroll
    for (int o = 4; o < 32; o <<= 1)
        lv += __shfl_xor_sync(0xFFFFFFFFu, lv, o);

    if (lane == 0) s_red[wid] = lv;
    __syncthreads();
    if (tid == 0) {
        float tot = 0.f;
        #pragma unroll
        for (int w = 0; w < 8; w++) tot += s_red[w];
        g_partials[blockIdx.x] = tot;
        __threadfence();
        int tk = atomicAdd(&g_ticket, 1);
        s_last = (tk == (int)gridDim.x - 1);
        if (s_last) g_ticket = 0;           // reset for next graph replay
    }
    __syncthreads();

    // ---- last block: deterministic fixed-order final reduction ----
    if (s_last) {
        volatile float* vp = g_partials;
        float v = 0.f;
        for (int i = tid; i < (int)gridDim.x; i += blockDim.x) v += vp[i];
        #pragma unroll
        for (int o = 16; o > 0; o >>= 1) v += __shfl_xor_sync(0xFFFFFFFFu, v, o);
        if (lane == 0) s_red[wid] = v;
        __syncthreads();
        if (tid == 0) {
            float tot = 0.f;
            #pragma unroll
            for (int w = 0; w < 8; w++) tot += s_red[w];
            float okl = __ldg(lck_p) + __ldg(kap_p)
                      - logf((float)B) - __ldg(lcz_p)
                      + tot / (float)NC;
            out[0] = okl;
        }
    }
}

// ---------------------------------------------------------------------------
extern "C" void kernel_launch(void* const* d_in, const int* in_sizes, int n_in,
                              void* d_out, int out_size)
{
    const float* mu  = (const float*)d_in[0];
    const float* z   = (const float*)d_in[1];
    const float* kap = (const float*)d_in[2];
    const float* lck = (const float*)d_in[3];
    const float* lcz = (const float*)d_in[4];

    const int B  = in_sizes[0] / DZ;    // 2048
    const int NC = in_sizes[1] / DZ;    // 65536 sample vectors
    const int ns = NC / B;              // samples per mu (32)

    vmf_prep_mu<<<(B + 7) / 8, 256>>>(mu, kap, B);

    const int grid = NC / 128;          // 128 z rows per block -> 512 CTAs
    vmf_main<<<grid, 256>>>(mu, z, kap, lck, lcz, (float*)d_out, B, NC, ns);
}